// round 3
// baseline (speedup 1.0000x reference)
#include <cuda_runtime.h>
#include <cuda_fp16.h>
#include <math.h>

// ---------------- scratch (device globals; no runtime allocation) ----------
__device__ float2 g_w2[128 * 256];             // packed fc1 weights [k][(sin_w, cos_w)]
__device__ float  g_xf[64 * 128 * 256];        // fc1 output
__device__ __half g_c1h[64 * 6 * 128 * 256];   // conv1 out (half)
__device__ float  g_p1[64 * 6 * 64 * 128];     // pool(relu(gn1(c1)))
__device__ __half g_c2h[64 * 24 * 64 * 128];   // conv2 out (half)
__device__ __half g_ah [64 * 24 * 32 * 64];    // silu(pool(relu(gn2))) (half)
__device__ __half g_u3h[64 * 24 * 64 * 128];   // tconv3 out (half)
__device__ __half g_u4h[64 * 12 * 128 * 256];  // tconv4 out (half)
__device__ float  g_u5[64 * 6 * 128 * 256];    // t5(gn4(...)) fp32

// per-block partial (sum, sumsq) buffers
__device__ float g_part1[8192 * 12];
__device__ float g_part2[2048 * 48];
__device__ float g_part3[1024 * 48];
__device__ float g_part4[4096 * 24];
__device__ float g_part5[8192 * 12];

__device__ float2 g_sumc1[64 * 6];
__device__ float2 g_sumc2[64 * 24];
__device__ float g_m3[64 * 6], g_r3[64 * 6];
__device__ float g_m4[64 * 6], g_r4[64 * 6];
__device__ float g_m5[64 * 6], g_r5[64 * 6];

// ---------------- deterministic block reduction (2 values) ------------------
__device__ __forceinline__ float2 block_reduce2(float s, float s2) {
    __shared__ float sh[64];
    int lane = threadIdx.x & 31, wid = threadIdx.x >> 5;
#pragma unroll
    for (int o = 16; o; o >>= 1) {
        s  += __shfl_xor_sync(0xffffffffu, s, o);
        s2 += __shfl_xor_sync(0xffffffffu, s2, o);
    }
    if (lane == 0) { sh[wid] = s; sh[wid + 32] = s2; }
    __syncthreads();
    if (threadIdx.x == 0) {
        float a = 0.f, b = 0.f;
        int nw = blockDim.x >> 5;
        for (int i = 0; i < nw; i++) { a += sh[i]; b += sh[i + 32]; }
        sh[0] = a; sh[32] = b;
    }
    __syncthreads();
    return make_float2(sh[0], sh[32]);
}

// ---------------- deterministic block reduction (N values, blockDim=256) ----
template <int N>
__device__ __forceinline__ void block_preduce(float (&v)[N], float* gdst) {
    __shared__ float red[8][N];
    int lane = threadIdx.x & 31, wid = threadIdx.x >> 5;
#pragma unroll
    for (int i = 0; i < N; i++) {
        float x = v[i];
#pragma unroll
        for (int o = 16; o; o >>= 1) x += __shfl_xor_sync(0xffffffffu, x, o);
        if (lane == 0) red[wid][i] = x;
    }
    __syncthreads();
    if (threadIdx.x < N) {
        float s = 0.f;
#pragma unroll
        for (int w = 0; w < 8; w++) s += red[w][threadIdx.x];
        gdst[threadIdx.x] = s;
    }
}

// ---------------- K0: pack fc1 weights as (sin, cos) pairs ------------------
__global__ void k_prepw(const float* __restrict__ w) {
    int i = blockIdx.x * 256 + threadIdx.x;      // 32768
    int k = i >> 8, n = i & 255;
    g_w2[k * 256 + n] = make_float2(w[n * 256 + k], w[n * 256 + k + 128]);
}

// ---------------- K1: Fourier embed + fc1 GEMM ------------------------------
// 512 blocks x 16 rows; thread = 2 rows x 8 cols
__global__ void __launch_bounds__(256) k_fc1(const float* __restrict__ x,
                                             const float* __restrict__ Wf,
                                             const float* __restrict__ fb) {
    __shared__ float2 ssc[16][32];
    int m0 = blockIdx.x * 16;
    int t = threadIdx.x, tc = t & 31, tr = t >> 5;
    float acc[2][8];
#pragma unroll
    for (int r = 0; r < 2; r++)
#pragma unroll
        for (int j = 0; j < 8; j++) acc[r][j] = 0.f;

    for (int k0 = 0; k0 < 128; k0 += 32) {
        if (k0) __syncthreads();
        for (int e = t; e < 512; e += 256) {
            int r = e >> 5, kk = e & 31;
            int m = m0 + r; int h = m & 127; int wc = k0 + kk;
            float p = x[m * 128 + wc] * Wf[h * 128 + wc] * 6.283185307179586f;
            float sv, cv; sincosf(p, &sv, &cv);
            ssc[r][kk] = make_float2(sv, cv);
        }
        __syncthreads();
#pragma unroll 4
        for (int kk = 0; kk < 32; kk++) {
            int k = k0 + kk;
            float2 w[8];
#pragma unroll
            for (int j = 0; j < 8; j++) w[j] = __ldg(&g_w2[k * 256 + tc + 32 * j]);
            float2 s0 = ssc[tr * 2][kk];
            float2 s1 = ssc[tr * 2 + 1][kk];
#pragma unroll
            for (int j = 0; j < 8; j++) {
                acc[0][j] = fmaf(s0.y, w[j].y, fmaf(s0.x, w[j].x, acc[0][j]));
                acc[1][j] = fmaf(s1.y, w[j].y, fmaf(s1.x, w[j].x, acc[1][j]));
            }
        }
    }
#pragma unroll
    for (int r = 0; r < 2; r++) {
        int m = m0 + tr * 2 + r;
#pragma unroll
        for (int j = 0; j < 8; j++) {
            int n = tc + 32 * j;
            g_xf[(size_t)m * 256 + n] = acc[r][j] + __ldg(&fb[n]);
        }
    }
}

// ---------------- K2: conv1 3x3, 1->6 ch + stats partials -------------------
__global__ void __launch_bounds__(256) k_conv1(const float* __restrict__ ck,
                                               const float* __restrict__ cb) {
    __shared__ float sw[9][6];
    __shared__ float sb[6];
    int t = threadIdx.x;
    if (t < 54) { int oc = t / 9, tap = t % 9; sw[tap][oc] = ck[t]; }
    if (t < 6) sb[t] = cb[t];
    __syncthreads();

    int idx = blockIdx.x * 256 + t;              // 64*128*256
    int w = idx & 255, h = (idx >> 8) & 127, b = idx >> 15;
    const float* in = g_xf + (size_t)b * 32768;
    float acc[6] = {0, 0, 0, 0, 0, 0};
    for (int ky = 0; ky < 3; ky++) {
        int hy = h + ky - 1; if ((unsigned)hy >= 128u) continue;
        for (int kx = 0; kx < 3; kx++) {
            int wx = w + kx - 1; if ((unsigned)wx >= 256u) continue;
            float v = in[hy * 256 + wx];
            const float* wp = &sw[ky * 3 + kx][0];
#pragma unroll
            for (int oc = 0; oc < 6; oc++) acc[oc] = fmaf(v, wp[oc], acc[oc]);
        }
    }
    size_t ob = (size_t)b * 6 * 32768 + h * 256 + w;
    float pv[12];
#pragma unroll
    for (int oc = 0; oc < 6; oc++) {
        __half hx = __float2half_rn(acc[oc] + sb[oc]);
        g_c1h[ob + (size_t)oc * 32768] = hx;
        float vr = __half2float(hx);
        pv[2 * oc] = vr; pv[2 * oc + 1] = vr * vr;
    }
    block_preduce<12>(pv, &g_part1[(size_t)blockIdx.x * 12]);
}

// ---------------- K3: GN1 (stats from partials) + ReLU + pool ---------------
__global__ void k_gnpool1(const float* __restrict__ gamma, const float* __restrict__ beta) {
    int bc = blockIdx.x; int c = bc % 6, b = bc / 6;
    float s = 0.f, s2 = 0.f;
    if (threadIdx.x < 128) {
        const float* pp = &g_part1[(size_t)(b * 128 + threadIdx.x) * 12 + 2 * c];
        s = pp[0]; s2 = pp[1];
    }
    float2 r = block_reduce2(s, s2);
    if (threadIdx.x == 0) g_sumc1[bc] = make_float2(r.x, r.y);
    float mean = r.x * (1.f / 32768.f);
    float rstd = rsqrtf(r.y * (1.f / 32768.f) - mean * mean + 1e-5f);
    float A = rstd * gamma[c], Bv = beta[c] - mean * A;

    const __half2* ph = (const __half2*)(g_c1h + (size_t)bc * 32768);
    float* q = g_p1 + (size_t)bc * 8192;
    for (int i = threadIdx.x; i < 8192; i += blockDim.x) {
        int ho = i >> 7, wo = i & 127;
        float2 a0 = __half22float2(ph[ho * 256 + wo]);
        float2 a1 = __half22float2(ph[ho * 256 + 128 + wo]);
        float v0 = fmaf(a0.x, A, Bv), v1 = fmaf(a0.y, A, Bv);
        float v2 = fmaf(a1.x, A, Bv), v3 = fmaf(a1.y, A, Bv);
        q[i] = fmaxf(fmaxf(fmaxf(v0, v1), fmaxf(v2, v3)), 0.f);
    }
}

// ---------------- K4: conv2 3x3, 6->24 ch + stats partials ------------------
__global__ void __launch_bounds__(256) k_conv2(const float* __restrict__ ck,
                                               const float* __restrict__ cb) {
    __shared__ float sw[9 * 6 * 24];
    __shared__ float sb[24];
    int t = threadIdx.x;
    for (int i = t; i < 1296; i += 256) {
        int kx = i % 3, ky = (i / 3) % 3, ic = (i / 9) % 6, oc = i / 54;
        sw[((ky * 3 + kx) * 6 + ic) * 24 + oc] = ck[i];
    }
    if (t < 24) sb[t] = cb[t];
    __syncthreads();

    int idx = blockIdx.x * 256 + t;              // 64*64*128
    int w = idx & 127, h = (idx >> 7) & 63, b = idx >> 13;
    const float* in = g_p1 + (size_t)b * 6 * 8192;
    float acc[24];
#pragma unroll
    for (int i = 0; i < 24; i++) acc[i] = 0.f;

    for (int ky = 0; ky < 3; ky++) {
        int hy = h + ky - 1; if ((unsigned)hy >= 64u) continue;
        for (int kx = 0; kx < 3; kx++) {
            int wx = w + kx - 1; if ((unsigned)wx >= 128u) continue;
            const float* wbase = &sw[(ky * 3 + kx) * 144];
#pragma unroll
            for (int ic = 0; ic < 6; ic++) {
                float v = in[(size_t)ic * 8192 + hy * 128 + wx];
                const float2* wp = (const float2*)(wbase + ic * 24);
#pragma unroll
                for (int j = 0; j < 12; j++) {
                    float2 w2 = wp[j];
                    acc[2 * j]     = fmaf(v, w2.x, acc[2 * j]);
                    acc[2 * j + 1] = fmaf(v, w2.y, acc[2 * j + 1]);
                }
            }
        }
    }
    size_t ob = (size_t)b * 24 * 8192 + h * 128 + w;
    float pv[48];
#pragma unroll
    for (int oc = 0; oc < 24; oc++) {
        __half hx = __float2half_rn(acc[oc] + sb[oc]);
        g_c2h[ob + (size_t)oc * 8192] = hx;
        float vr = __half2float(hx);
        pv[2 * oc] = vr; pv[2 * oc + 1] = vr * vr;
    }
    block_preduce<48>(pv, &g_part2[(size_t)blockIdx.x * 48]);
}

// ---------------- K5: GN2 + ReLU + pool + SiLU ------------------------------
__global__ void k_gnpool2(const float* __restrict__ gamma, const float* __restrict__ beta) {
    int bc = blockIdx.x; int c = bc % 24, b = bc / 24;
    float s = 0.f, s2 = 0.f;
    if (threadIdx.x < 32) {
        const float* pp = &g_part2[(size_t)(b * 32 + threadIdx.x) * 48 + 2 * c];
        s = pp[0]; s2 = pp[1];
    }
    float2 r = block_reduce2(s, s2);
    if (threadIdx.x == 0) g_sumc2[bc] = make_float2(r.x, r.y);
    float mean = r.x * (1.f / 8192.f);
    float rstd = rsqrtf(r.y * (1.f / 8192.f) - mean * mean + 1e-5f);
    float A = rstd * gamma[c], Bv = beta[c] - mean * A;

    const __half2* ph = (const __half2*)(g_c2h + (size_t)bc * 8192);
    __half* q = g_ah + (size_t)bc * 2048;
    for (int i = threadIdx.x; i < 2048; i += blockDim.x) {
        int ho = i >> 6, wo = i & 63;
        float2 a0 = __half22float2(ph[ho * 128 + wo]);
        float2 a1 = __half22float2(ph[ho * 128 + 64 + wo]);
        float v0 = fmaf(a0.x, A, Bv), v1 = fmaf(a0.y, A, Bv);
        float v2 = fmaf(a1.x, A, Bv), v3 = fmaf(a1.y, A, Bv);
        float v = fmaxf(fmaxf(fmaxf(v0, v1), fmaxf(v2, v3)), 0.f);
        q[i] = __float2half_rn(v / (1.f + expf(-v)));
    }
}

// ---------------- K6: tconv3 2x2 s2, 24->24 + stats partials ----------------
__global__ void __launch_bounds__(256) k_t3(const float* __restrict__ tk,
                                            const float* __restrict__ tb) {
    __shared__ float sw[2304];                   // [d][ic][oc][q]
    __shared__ float sb[24];
    int t = threadIdx.x;
    for (int i = t; i < 2304; i += 256) {
        int q = i & 1, d = (i >> 1) & 1, oc = (i >> 2) % 24, ic = i / 96;
        sw[((d * 24 + ic) * 24 + oc) * 2 + q] = tk[i];
    }
    if (t < 24) sb[t] = tb[t];
    __syncthreads();

    int idx = blockIdx.x * 256 + t;              // 64*64*64
    int wi = idx & 63, h = (idx >> 6) & 63, b = idx >> 12;
    int d = h & 1, hi = h >> 1;
    float acc[48];
#pragma unroll
    for (int i = 0; i < 48; i++) acc[i] = 0.f;

    const __half* base = g_ah + (size_t)b * 24 * 2048 + hi * 64 + wi;
    const float* wb = sw + d * 24 * 48;
#pragma unroll 4
    for (int ic = 0; ic < 24; ic++) {
        float v = __half2float(base[(size_t)ic * 2048]);
        const float2* wp = (const float2*)(wb + ic * 48);
#pragma unroll
        for (int oc = 0; oc < 24; oc++) {
            float2 w2 = wp[oc];
            acc[2 * oc]     = fmaf(v, w2.x, acc[2 * oc]);
            acc[2 * oc + 1] = fmaf(v, w2.y, acc[2 * oc + 1]);
        }
    }
    __half* ob = g_u3h + (size_t)b * 24 * 8192 + h * 128 + 2 * wi;
    float pv[48];
#pragma unroll
    for (int oc = 0; oc < 24; oc++) {
        float bv = sb[oc];
        __half2 h2 = __floats2half2_rn(acc[2 * oc] + bv, acc[2 * oc + 1] + bv);
        *(__half2*)(ob + (size_t)oc * 8192) = h2;
        float2 yr = __half22float2(h2);
        pv[2 * oc] = yr.x + yr.y; pv[2 * oc + 1] = fmaf(yr.x, yr.x, yr.y * yr.y);
    }
    block_preduce<48>(pv, &g_part3[(size_t)blockIdx.x * 48]);
}

// ---------------- K7: gn3 stats reduce --------------------------------------
__global__ void k_red3() {
    int bg = blockIdx.x; int b = bg / 6, g = bg % 6;
    float s = 0.f, s2 = 0.f;
    if (g < 3) {
        if (threadIdx.x < 8) {
            float2 v = g_sumc2[b * 24 + g * 8 + threadIdx.x];
            s = v.x; s2 = v.y;
        }
    } else {
        if (threadIdx.x < 128) {
            int j = threadIdx.x >> 4, blk = threadIdx.x & 15;
            int oc = (g - 3) * 8 + j;
            const float* p = &g_part3[(size_t)(b * 16 + blk) * 48 + oc * 2];
            s = p[0]; s2 = p[1];
        }
    }
    float2 r = block_reduce2(s, s2);
    if (threadIdx.x == 0) {
        float mean = r.x * (1.f / 65536.f);
        float rstd = rsqrtf(r.y * (1.f / 65536.f) - mean * mean + 1e-5f);
        g_m3[bg] = mean; g_r3[bg] = rstd;
    }
}

// ---------------- K8: tconv4 2x2 s2, 48->12 with GN3 folded in --------------
__global__ void __launch_bounds__(256) k_t4(const float* __restrict__ tk,
                                            const float* __restrict__ tb,
                                            const float* __restrict__ g3g,
                                            const float* __restrict__ g3b) {
    __shared__ float sw[2304];                   // folded weights [d][ic][oc][q]
    __shared__ float sbias[2][12][2];
    __shared__ float sA[48], sB[48];
    int t = threadIdx.x;
    int b = blockIdx.x >> 6;

    if (t < 48) {
        int g = t >> 3;
        float A = g_r3[b * 6 + g] * g3g[t];
        sA[t] = A;
        sB[t] = g3b[t] - g_m3[b * 6 + g] * A;
    }
    __syncthreads();
    for (int i = t; i < 2304; i += 256) {
        int q = i & 1, d = (i >> 1) & 1, oc = (i >> 2) % 12, ic = i / 48;
        sw[((d * 48 + ic) * 12 + oc) * 2 + q] = sA[ic] * tk[i];
    }
    if (t < 48) {
        int q = t & 1, d = (t >> 1) & 1, oc = t >> 2;
        float bsum = tb[oc];
        for (int ic = 0; ic < 48; ic++)
            bsum = fmaf(sB[ic], tk[((ic * 12 + oc) * 2 + d) * 2 + q], bsum);
        sbias[d][oc][q] = bsum;
    }
    __syncthreads();

    int idx = blockIdx.x * 256 + t;              // 64*128*128
    int wi = idx & 127, h = (idx >> 7) & 127;
    int d = h & 1, hi = h >> 1;
    float acc[24];
#pragma unroll
    for (int i = 0; i < 24; i++) acc[i] = 0.f;

    const __half* c2b = g_c2h + (size_t)b * 24 * 8192 + hi * 128 + wi;
    const __half* u3b = g_u3h + (size_t)b * 24 * 8192 + hi * 128 + wi;
    const float* wb = sw + d * 48 * 24;
#pragma unroll 6
    for (int ic = 0; ic < 24; ic++) {
        float v = __half2float(c2b[(size_t)ic * 8192]);
        const float2* wp = (const float2*)(wb + ic * 24);
#pragma unroll
        for (int oc = 0; oc < 12; oc++) {
            float2 w2 = wp[oc];
            acc[2 * oc]     = fmaf(v, w2.x, acc[2 * oc]);
            acc[2 * oc + 1] = fmaf(v, w2.y, acc[2 * oc + 1]);
        }
    }
#pragma unroll 6
    for (int ic = 0; ic < 24; ic++) {
        float v = __half2float(u3b[(size_t)ic * 8192]);
        const float2* wp = (const float2*)(wb + (24 + ic) * 24);
#pragma unroll
        for (int oc = 0; oc < 12; oc++) {
            float2 w2 = wp[oc];
            acc[2 * oc]     = fmaf(v, w2.x, acc[2 * oc]);
            acc[2 * oc + 1] = fmaf(v, w2.y, acc[2 * oc + 1]);
        }
    }
    __half* ob = g_u4h + (size_t)b * 12 * 32768 + (size_t)h * 256 + 2 * wi;
    float pv[24];
#pragma unroll
    for (int oc = 0; oc < 12; oc++) {
        float y0 = acc[2 * oc] + sbias[d][oc][0];
        float y1 = acc[2 * oc + 1] + sbias[d][oc][1];
        __half2 h2 = __floats2half2_rn(y0, y1);
        *(__half2*)(ob + (size_t)oc * 32768) = h2;
        float2 yr = __half22float2(h2);
        pv[2 * oc] = yr.x + yr.y; pv[2 * oc + 1] = fmaf(yr.x, yr.x, yr.y * yr.y);
    }
    block_preduce<24>(pv, &g_part4[(size_t)blockIdx.x * 24]);
}

// ---------------- K9: gn4 stats reduce ---------------------------------------
__global__ void k_red4() {
    int bg = blockIdx.x; int b = bg / 6, g = bg % 6;
    float s = 0.f, s2 = 0.f;
    if (g < 2) {
        if (threadIdx.x < 3) {
            float2 v = g_sumc1[b * 6 + g * 3 + threadIdx.x];
            s = v.x; s2 = v.y;
        }
    } else {
        if (threadIdx.x < 192) {
            int j = threadIdx.x >> 6, blk = threadIdx.x & 63;
            int oc = (g - 2) * 3 + j;
            const float* p = &g_part4[(size_t)(b * 64 + blk) * 24 + oc * 2];
            s = p[0]; s2 = p[1];
        }
    }
    float2 r = block_reduce2(s, s2);
    if (threadIdx.x == 0) {
        float mean = r.x * (1.f / 98304.f);
        float rstd = rsqrtf(r.y * (1.f / 98304.f) - mean * mean + 1e-5f);
        g_m4[bg] = mean; g_r4[bg] = rstd;
    }
}

// ---------------- K10: GN4-apply fused with t5 1x1 (18->6) ------------------
__global__ void __launch_bounds__(256) k_gn4t5(const float* __restrict__ g4g,
                                               const float* __restrict__ g4b,
                                               const float* __restrict__ t5k,
                                               const float* __restrict__ t5b) {
    __shared__ float W2[18][6];
    __shared__ float cst[6];
    int t = threadIdx.x;
    int b  = blockIdx.x >> 7;
    int sp = ((blockIdx.x & 127) << 8) + t;

    if (t < 108) {
        int c = t / 6, o = t % 6;
        float A = g_r4[b * 6 + c / 3] * g4g[c];
        W2[c][o] = A * t5k[o * 18 + c];
    }
    if (t >= 128 && t < 134) {
        int o = t - 128;
        float cc = t5b[o];
        for (int c = 0; c < 18; c++) {
            float A  = g_r4[b * 6 + c / 3] * g4g[c];
            float Bv = g4b[c] - g_m4[b * 6 + c / 3] * A;
            cc = fmaf(Bv, t5k[o * 18 + c], cc);
        }
        cst[o] = cc;
    }
    __syncthreads();

    float o0 = cst[0], o1 = cst[1], o2 = cst[2], o3 = cst[3], o4 = cst[4], o5 = cst[5];
    const __half* c1b = g_c1h + (size_t)b * 6 * 32768 + sp;
    const __half* u4b = g_u4h + (size_t)b * 12 * 32768 + sp;
#pragma unroll
    for (int c = 0; c < 18; c++) {
        float v = __half2float((c < 6) ? c1b[(size_t)c * 32768] : u4b[(size_t)(c - 6) * 32768]);
        const float* wr = &W2[c][0];
        o0 = fmaf(v, wr[0], o0); o1 = fmaf(v, wr[1], o1); o2 = fmaf(v, wr[2], o2);
        o3 = fmaf(v, wr[3], o3); o4 = fmaf(v, wr[4], o4); o5 = fmaf(v, wr[5], o5);
    }
    float* up = g_u5 + (size_t)b * 6 * 32768 + sp;
    up[0] = o0; up[32768] = o1; up[2 * 32768] = o2;
    up[3 * 32768] = o3; up[4 * 32768] = o4; up[5 * 32768] = o5;

    float pv[12];
    pv[0] = o0; pv[1] = o0 * o0; pv[2]  = o1; pv[3]  = o1 * o1;
    pv[4] = o2; pv[5] = o2 * o2; pv[6]  = o3; pv[7]  = o3 * o3;
    pv[8] = o4; pv[9] = o4 * o4; pv[10] = o5; pv[11] = o5 * o5;
    block_preduce<12>(pv, &g_part5[(size_t)blockIdx.x * 12]);
}

// ---------------- K11: gn5 stats reduce --------------------------------------
__global__ void k_red5() {
    int bc = blockIdx.x; int b = bc / 6, c = bc % 6;
    float s = 0.f, s2 = 0.f;
    if (threadIdx.x < 128) {
        const float* p = &g_part5[(size_t)(b * 128 + threadIdx.x) * 12 + 2 * c];
        s = p[0]; s2 = p[1];
    }
    float2 r = block_reduce2(s, s2);
    if (threadIdx.x == 0) {
        float mean = r.x * (1.f / 32768.f);
        float rstd = rsqrtf(r.y * (1.f / 32768.f) - mean * mean + 1e-5f);
        g_m5[bc] = mean; g_r5[bc] = rstd;
    }
}

// ---------------- K12: GN5-apply + final 1x1 (6->1) + /std(t) ---------------
__global__ void __launch_bounds__(256) k_final(const float* __restrict__ tt,
                                               const float* __restrict__ g5g,
                                               const float* __restrict__ g5b,
                                               const float* __restrict__ fk,
                                               const float* __restrict__ fb2,
                                               float* __restrict__ out) {
    __shared__ float coef[6];
    __shared__ float cshift, istd;
    int t = threadIdx.x;
    int b  = blockIdx.x >> 7;
    int sp = ((blockIdx.x & 127) << 8) + t;

    if (t < 6) {
        float A = g_r5[b * 6 + t] * g5g[t];
        coef[t] = A * fk[t];
    }
    if (t == 6) {
        float cc = fb2[0];
        for (int c = 0; c < 6; c++) {
            float A = g_r5[b * 6 + c] * g5g[c];
            cc = fmaf(g5b[c] - g_m5[b * 6 + c] * A, fk[c], cc);
        }
        cshift = cc;
    }
    if (t == 7) {
        float tv = tt[b];
        float s2v = (expf(tv * 6.437751649736401f) - 1.f) * (1.f / 6.437751649736401f);
        istd = rsqrtf(s2v);
    }
    __syncthreads();

    const float* up = g_u5 + (size_t)b * 6 * 32768 + sp;
    float v = cshift;
#pragma unroll
    for (int c = 0; c < 6; c++) v = fmaf(up[(size_t)c * 32768], coef[c], v);
    out[(size_t)b * 32768 + sp] = v * istd;
}

// ---------------- launcher ---------------------------------------------------
extern "C" void kernel_launch(void* const* d_in, const int* in_sizes, int n_in,
                              void* d_out, int out_size) {
    const float* x       = (const float*)d_in[0];
    const float* t       = (const float*)d_in[1];
    const float* Wf      = (const float*)d_in[2];
    const float* fc1_w   = (const float*)d_in[3];
    const float* fc1_b   = (const float*)d_in[4];
    const float* conv1_k = (const float*)d_in[5];
    const float* conv1_b = (const float*)d_in[6];
    const float* gn1_g   = (const float*)d_in[7];
    const float* gn1_b   = (const float*)d_in[8];
    const float* conv2_k = (const float*)d_in[9];
    const float* conv2_b = (const float*)d_in[10];
    const float* gn2_g   = (const float*)d_in[11];
    const float* gn2_b   = (const float*)d_in[12];
    const float* t3_k    = (const float*)d_in[13];
    const float* t3_b    = (const float*)d_in[14];
    const float* gn3_g   = (const float*)d_in[15];
    const float* gn3_b   = (const float*)d_in[16];
    const float* t4_k    = (const float*)d_in[17];
    const float* t4_b    = (const float*)d_in[18];
    const float* gn4_g   = (const float*)d_in[19];
    const float* gn4_b   = (const float*)d_in[20];
    const float* t5_k    = (const float*)d_in[21];
    const float* t5_b    = (const float*)d_in[22];
    const float* gn5_g   = (const float*)d_in[23];
    const float* gn5_b   = (const float*)d_in[24];
    const float* fin_k   = (const float*)d_in[25];
    const float* fin_b   = (const float*)d_in[26];
    float* out = (float*)d_out;

    k_prepw<<<128, 256>>>(fc1_w);
    k_fc1<<<512, 256>>>(x, Wf, fc1_b);
    k_conv1<<<8192, 256>>>(conv1_k, conv1_b);
    k_gnpool1<<<384, 512>>>(gn1_g, gn1_b);
    k_conv2<<<2048, 256>>>(conv2_k, conv2_b);
    k_gnpool2<<<1536, 512>>>(gn2_g, gn2_b);
    k_t3<<<1024, 256>>>(t3_k, t3_b);
    k_red3<<<384, 128>>>();
    k_t4<<<4096, 256>>>(t4_k, t4_b, gn3_g, gn3_b);
    k_red4<<<384, 256>>>();
    k_gn4t5<<<8192, 256>>>(gn4_g, gn4_b, t5_k, t5_b);
    k_red5<<<384, 128>>>();
    k_final<<<8192, 256>>>(t, gn5_g, gn5_b, fin_k, fin_b, out);
}

// round 4
// speedup vs baseline: 1.0188x; 1.0188x over previous
#include <cuda_runtime.h>
#include <cuda_fp16.h>
#include <math.h>

typedef unsigned long long u64;

// ---- packed f32x2 helpers (sm_103a FFMA2) ----------------------------------
__device__ __forceinline__ u64 pk2(float x, float y) {
    u64 r; asm("mov.b64 %0,{%1,%2};" : "=l"(r) : "f"(x), "f"(y)); return r;
}
__device__ __forceinline__ float2 upk2(u64 v) {
    float2 r; asm("mov.b64 {%0,%1},%2;" : "=f"(r.x), "=f"(r.y) : "l"(v)); return r;
}
__device__ __forceinline__ u64 ffma2(u64 a, u64 b, u64 c) {
    u64 d; asm("fma.rn.f32x2 %0,%1,%2,%3;" : "=l"(d) : "l"(a), "l"(b), "l"(c)); return d;
}

// ---------------- scratch ----------------------------------------------------
__device__ float  g_ws[128 * 256];             // fc1 sin-weights [k][n]
__device__ float  g_wc[128 * 256];             // fc1 cos-weights [k][n]
__device__ float  g_xf[64 * 128 * 256];        // fc1 output
__device__ __half g_c1h[64 * 6 * 128 * 256];   // conv1 out (half)
__device__ float  g_p1[64 * 6 * 64 * 128];     // pool(relu(gn1))
__device__ float  g_c2[64 * 24 * 64 * 128];    // conv2 out (fp32)
__device__ float  g_a [64 * 24 * 32 * 64];     // silu(pool(relu(gn2))) fp32
__device__ float  g_u3[64 * 24 * 64 * 128];    // tconv3 out fp32
__device__ __half g_u4h[64 * 12 * 128 * 256];  // tconv4 out (half)
__device__ float  g_u5[64 * 6 * 128 * 256];    // t5(gn4(...)) fp32

__device__ float g_part1[8192 * 12];
__device__ float g_part2[2048 * 48];
__device__ float g_part3[1024 * 48];
__device__ float g_part4[4096 * 24];
__device__ float g_part5[8192 * 12];

__device__ float2 g_sumc1[64 * 6];
__device__ float2 g_sumc2[64 * 24];
__device__ float g_m3[64 * 6], g_r3[64 * 6];
__device__ float g_m4[64 * 6], g_r4[64 * 6];
__device__ float g_m5[64 * 6], g_r5[64 * 6];

// ---------------- deterministic block reduction (2 values) ------------------
__device__ __forceinline__ float2 block_reduce2(float s, float s2) {
    __shared__ float sh[64];
    int lane = threadIdx.x & 31, wid = threadIdx.x >> 5;
#pragma unroll
    for (int o = 16; o; o >>= 1) {
        s  += __shfl_xor_sync(0xffffffffu, s, o);
        s2 += __shfl_xor_sync(0xffffffffu, s2, o);
    }
    if (lane == 0) { sh[wid] = s; sh[wid + 32] = s2; }
    __syncthreads();
    if (threadIdx.x == 0) {
        float a = 0.f, b = 0.f;
        int nw = blockDim.x >> 5;
        for (int i = 0; i < nw; i++) { a += sh[i]; b += sh[i + 32]; }
        sh[0] = a; sh[32] = b;
    }
    __syncthreads();
    return make_float2(sh[0], sh[32]);
}

template <int N>
__device__ __forceinline__ void block_preduce(float (&v)[N], float* gdst) {
    __shared__ float red[8][N];
    int lane = threadIdx.x & 31, wid = threadIdx.x >> 5;
#pragma unroll
    for (int i = 0; i < N; i++) {
        float x = v[i];
#pragma unroll
        for (int o = 16; o; o >>= 1) x += __shfl_xor_sync(0xffffffffu, x, o);
        if (lane == 0) red[wid][i] = x;
    }
    __syncthreads();
    if (threadIdx.x < N) {
        float s = 0.f;
#pragma unroll
        for (int w = 0; w < 8; w++) s += red[w][threadIdx.x];
        gdst[threadIdx.x] = s;
    }
}

// ---------------- K0: split fc1 weights into sin/cos planes -----------------
__global__ void k_prepw(const float* __restrict__ w) {
    int i = blockIdx.x * 256 + threadIdx.x;      // 32768
    int k = i >> 8, n = i & 255;
    g_ws[k * 256 + n] = w[n * 256 + k];
    g_wc[k * 256 + n] = w[n * 256 + k + 128];
}

// ---------------- K1: Fourier embed + fc1 GEMM (FFMA2) ----------------------
// 512 blocks x 16 rows; thread = 2 rows x 4 col-pairs (pair p -> cols 2p,2p+1)
__global__ void __launch_bounds__(256) k_fc1(const float* __restrict__ x,
                                             const float* __restrict__ Wf,
                                             const float* __restrict__ fb) {
    __shared__ float2 ssc[16][32];
    int m0 = blockIdx.x * 16;
    int t = threadIdx.x, tc = t & 31, tr = t >> 5;
    u64 acc[2][4];
    u64 z = pk2(0.f, 0.f);
#pragma unroll
    for (int r = 0; r < 2; r++)
#pragma unroll
        for (int j = 0; j < 4; j++) acc[r][j] = z;

    const u64* Ws = (const u64*)g_ws;
    const u64* Wc = (const u64*)g_wc;

    for (int k0 = 0; k0 < 128; k0 += 32) {
        if (k0) __syncthreads();
        for (int e = t; e < 512; e += 256) {
            int r = e >> 5, kk = e & 31;
            int m = m0 + r; int h = m & 127; int wcn = k0 + kk;
            float p = x[m * 128 + wcn] * Wf[h * 128 + wcn] * 6.283185307179586f;
            float sv, cv; sincosf(p, &sv, &cv);
            ssc[r][kk] = make_float2(sv, cv);
        }
        __syncthreads();
#pragma unroll 4
        for (int kk = 0; kk < 32; kk++) {
            int k = k0 + kk;
            u64 ws[4], wc[4];
#pragma unroll
            for (int j = 0; j < 4; j++) {
                ws[j] = __ldg(&Ws[k * 128 + tc + 32 * j]);
                wc[j] = __ldg(&Wc[k * 128 + tc + 32 * j]);
            }
            float2 s0 = ssc[tr * 2][kk];
            float2 s1 = ssc[tr * 2 + 1][kk];
            u64 s0x = pk2(s0.x, s0.x), s0y = pk2(s0.y, s0.y);
            u64 s1x = pk2(s1.x, s1.x), s1y = pk2(s1.y, s1.y);
#pragma unroll
            for (int j = 0; j < 4; j++) {
                acc[0][j] = ffma2(s0x, ws[j], acc[0][j]);
                acc[0][j] = ffma2(s0y, wc[j], acc[0][j]);
                acc[1][j] = ffma2(s1x, ws[j], acc[1][j]);
                acc[1][j] = ffma2(s1y, wc[j], acc[1][j]);
            }
        }
    }
    const float2* fb2 = (const float2*)fb;
#pragma unroll
    for (int r = 0; r < 2; r++) {
        int m = m0 + tr * 2 + r;
#pragma unroll
        for (int j = 0; j < 4; j++) {
            int p = tc + 32 * j;                 // pair index
            float2 a = upk2(acc[r][j]);
            float2 bi = __ldg(&fb2[p]);
            *(float2*)&g_xf[(size_t)m * 256 + 2 * p] = make_float2(a.x + bi.x, a.y + bi.y);
        }
    }
}

// ---------------- K2: conv1 3x3, 1->6 ch (FFMA2) + stats --------------------
__global__ void __launch_bounds__(256) k_conv1(const float* __restrict__ ck,
                                               const float* __restrict__ cb) {
    __shared__ float sw[9][6];                   // rows 24B apart -> pairs 8B aligned
    __shared__ float sb[6];
    int t = threadIdx.x;
    if (t < 54) { int oc = t / 9, tap = t % 9; sw[tap][oc] = ck[t]; }
    if (t < 6) sb[t] = cb[t];
    __syncthreads();

    int idx = blockIdx.x * 256 + t;              // 64*128*256
    int w = idx & 255, h = (idx >> 8) & 127, b = idx >> 15;
    const float* in = g_xf + (size_t)b * 32768;
    u64 acc[3];
    u64 z = pk2(0.f, 0.f);
    acc[0] = z; acc[1] = z; acc[2] = z;
    for (int ky = 0; ky < 3; ky++) {
        int hy = h + ky - 1; if ((unsigned)hy >= 128u) continue;
        for (int kx = 0; kx < 3; kx++) {
            int wx = w + kx - 1; if ((unsigned)wx >= 256u) continue;
            float v = in[hy * 256 + wx];
            u64 vv = pk2(v, v);
            const u64* wp = (const u64*)&sw[ky * 3 + kx][0];
#pragma unroll
            for (int j = 0; j < 3; j++) acc[j] = ffma2(vv, wp[j], acc[j]);
        }
    }
    size_t ob = (size_t)b * 6 * 32768 + h * 256 + w;
    float pv[12];
#pragma unroll
    for (int j = 0; j < 3; j++) {
        float2 a = upk2(acc[j]);
        float y0 = a.x + sb[2 * j], y1 = a.y + sb[2 * j + 1];
        __half h0 = __float2half_rn(y0), h1 = __float2half_rn(y1);
        g_c1h[ob + (size_t)(2 * j) * 32768] = h0;
        g_c1h[ob + (size_t)(2 * j + 1) * 32768] = h1;
        float r0 = __half2float(h0), r1 = __half2float(h1);
        pv[4 * j] = r0; pv[4 * j + 1] = r0 * r0;
        pv[4 * j + 2] = r1; pv[4 * j + 3] = r1 * r1;
    }
    block_preduce<12>(pv, &g_part1[(size_t)blockIdx.x * 12]);
}

// ---------------- K3: GN1 + ReLU + pool (4-way spatial split) ---------------
__global__ void __launch_bounds__(256) k_gnpool1(const float* __restrict__ gamma,
                                                 const float* __restrict__ beta) {
    int bc = blockIdx.x >> 2, quarter = blockIdx.x & 3;
    int c = bc % 6, b = bc / 6;
    float s = 0.f, s2 = 0.f;
    if (threadIdx.x < 128) {
        const float* pp = &g_part1[(size_t)(b * 128 + threadIdx.x) * 12 + 2 * c];
        s = pp[0]; s2 = pp[1];
    }
    float2 r = block_reduce2(s, s2);
    if (quarter == 0 && threadIdx.x == 0) g_sumc1[bc] = make_float2(r.x, r.y);
    float mean = r.x * (1.f / 32768.f);
    float rstd = rsqrtf(r.y * (1.f / 32768.f) - mean * mean + 1e-5f);
    float A = rstd * gamma[c], Bv = beta[c] - mean * A;

    const __half2* ph = (const __half2*)(g_c1h + (size_t)bc * 32768);
    float* q = g_p1 + (size_t)bc * 8192;
    int i0 = quarter * 2048;
    for (int i = i0 + threadIdx.x; i < i0 + 2048; i += 256) {
        int ho = i >> 7, wo = i & 127;
        float2 a0 = __half22float2(ph[ho * 256 + wo]);
        float2 a1 = __half22float2(ph[ho * 256 + 128 + wo]);
        float v0 = fmaf(a0.x, A, Bv), v1 = fmaf(a0.y, A, Bv);
        float v2 = fmaf(a1.x, A, Bv), v3 = fmaf(a1.y, A, Bv);
        q[i] = fmaxf(fmaxf(fmaxf(v0, v1), fmaxf(v2, v3)), 0.f);
    }
}

// ---------------- K4: conv2 3x3, 6->24 ch (FFMA2) + stats -------------------
__global__ void __launch_bounds__(256) k_conv2(const float* __restrict__ ck,
                                               const float* __restrict__ cb) {
    __shared__ float sw[9 * 6 * 24];
    __shared__ float sb[24];
    int t = threadIdx.x;
    for (int i = t; i < 1296; i += 256) {
        int kx = i % 3, ky = (i / 3) % 3, ic = (i / 9) % 6, oc = i / 54;
        sw[((ky * 3 + kx) * 6 + ic) * 24 + oc] = ck[i];
    }
    if (t < 24) sb[t] = cb[t];
    __syncthreads();

    int idx = blockIdx.x * 256 + t;              // 64*64*128
    int w = idx & 127, h = (idx >> 7) & 63, b = idx >> 13;
    const float* in = g_p1 + (size_t)b * 6 * 8192;
    u64 acc[12];
    u64 z = pk2(0.f, 0.f);
#pragma unroll
    for (int i = 0; i < 12; i++) acc[i] = z;

    for (int ky = 0; ky < 3; ky++) {
        int hy = h + ky - 1; if ((unsigned)hy >= 64u) continue;
        for (int kx = 0; kx < 3; kx++) {
            int wx = w + kx - 1; if ((unsigned)wx >= 128u) continue;
            const float* wbase = &sw[(ky * 3 + kx) * 144];
#pragma unroll
            for (int ic = 0; ic < 6; ic++) {
                float v = in[(size_t)ic * 8192 + hy * 128 + wx];
                u64 vv = pk2(v, v);
                const u64* wp = (const u64*)(wbase + ic * 24);
#pragma unroll
                for (int j = 0; j < 12; j++) acc[j] = ffma2(vv, wp[j], acc[j]);
            }
        }
    }
    size_t ob = (size_t)b * 24 * 8192 + h * 128 + w;
    float pv[48];
#pragma unroll
    for (int j = 0; j < 12; j++) {
        float2 a = upk2(acc[j]);
        float y0 = a.x + sb[2 * j], y1 = a.y + sb[2 * j + 1];
        g_c2[ob + (size_t)(2 * j) * 8192] = y0;
        g_c2[ob + (size_t)(2 * j + 1) * 8192] = y1;
        pv[4 * j] = y0; pv[4 * j + 1] = y0 * y0;
        pv[4 * j + 2] = y1; pv[4 * j + 3] = y1 * y1;
    }
    block_preduce<48>(pv, &g_part2[(size_t)blockIdx.x * 48]);
}

// ---------------- K5: GN2 + ReLU + pool + SiLU ------------------------------
__global__ void k_gnpool2(const float* __restrict__ gamma, const float* __restrict__ beta) {
    int bc = blockIdx.x; int c = bc % 24, b = bc / 24;
    float s = 0.f, s2 = 0.f;
    if (threadIdx.x < 32) {
        const float* pp = &g_part2[(size_t)(b * 32 + threadIdx.x) * 48 + 2 * c];
        s = pp[0]; s2 = pp[1];
    }
    float2 r = block_reduce2(s, s2);
    if (threadIdx.x == 0) g_sumc2[bc] = make_float2(r.x, r.y);
    float mean = r.x * (1.f / 8192.f);
    float rstd = rsqrtf(r.y * (1.f / 8192.f) - mean * mean + 1e-5f);
    float A = rstd * gamma[c], Bv = beta[c] - mean * A;

    const float* p = g_c2 + (size_t)bc * 8192;
    float* q = g_a + (size_t)bc * 2048;
    for (int i = threadIdx.x; i < 2048; i += blockDim.x) {
        int ho = i >> 6, wo = i & 63;
        const float* rp = p + ho * 256 + wo * 2;
        float2 a0 = *(const float2*)rp;
        float2 a1 = *(const float2*)(rp + 128);
        float v0 = fmaf(a0.x, A, Bv), v1 = fmaf(a0.y, A, Bv);
        float v2 = fmaf(a1.x, A, Bv), v3 = fmaf(a1.y, A, Bv);
        float v = fmaxf(fmaxf(fmaxf(v0, v1), fmaxf(v2, v3)), 0.f);
        q[i] = v / (1.f + expf(-v));
    }
}

// ---------------- K6: tconv3 2x2 s2, 24->24 (FFMA2) + stats -----------------
__global__ void __launch_bounds__(256) k_t3(const float* __restrict__ tk,
                                            const float* __restrict__ tb) {
    __shared__ float sw[2304];                   // [d][ic][oc][q], (q0,q1) pairs
    __shared__ float sb[24];
    int t = threadIdx.x;
    for (int i = t; i < 2304; i += 256) {
        int q = i & 1, d = (i >> 1) & 1, oc = (i >> 2) % 24, ic = i / 96;
        sw[((d * 24 + ic) * 24 + oc) * 2 + q] = tk[i];
    }
    if (t < 24) sb[t] = tb[t];
    __syncthreads();

    int idx = blockIdx.x * 256 + t;              // 64*64*64
    int wi = idx & 63, h = (idx >> 6) & 63, b = idx >> 12;
    int d = h & 1, hi = h >> 1;
    u64 acc[24];
    u64 z = pk2(0.f, 0.f);
#pragma unroll
    for (int i = 0; i < 24; i++) acc[i] = z;

    const float* base = g_a + (size_t)b * 24 * 2048 + hi * 64 + wi;
    const u64* wb = (const u64*)(sw + d * 24 * 48);
#pragma unroll 4
    for (int ic = 0; ic < 24; ic++) {
        float v = base[(size_t)ic * 2048];
        u64 vv = pk2(v, v);
        const u64* wp = wb + ic * 24;
#pragma unroll
        for (int oc = 0; oc < 24; oc++) acc[oc] = ffma2(vv, wp[oc], acc[oc]);
    }
    float* ob = g_u3 + (size_t)b * 24 * 8192 + h * 128 + 2 * wi;
    float pv[48];
#pragma unroll
    for (int oc = 0; oc < 24; oc++) {
        float bv = sb[oc];
        float2 a = upk2(acc[oc]);
        float y0 = a.x + bv, y1 = a.y + bv;
        *(float2*)(ob + (size_t)oc * 8192) = make_float2(y0, y1);
        pv[2 * oc] = y0 + y1; pv[2 * oc + 1] = fmaf(y0, y0, y1 * y1);
    }
    block_preduce<48>(pv, &g_part3[(size_t)blockIdx.x * 48]);
}

// ---------------- K7: gn3 stats reduce --------------------------------------
__global__ void k_red3() {
    int bg = blockIdx.x; int b = bg / 6, g = bg % 6;
    float s = 0.f, s2 = 0.f;
    if (g < 3) {
        if (threadIdx.x < 8) {
            float2 v = g_sumc2[b * 24 + g * 8 + threadIdx.x];
            s = v.x; s2 = v.y;
        }
    } else {
        if (threadIdx.x < 128) {
            int j = threadIdx.x >> 4, blk = threadIdx.x & 15;
            int oc = (g - 3) * 8 + j;
            const float* p = &g_part3[(size_t)(b * 16 + blk) * 48 + oc * 2];
            s = p[0]; s2 = p[1];
        }
    }
    float2 r = block_reduce2(s, s2);
    if (threadIdx.x == 0) {
        float mean = r.x * (1.f / 65536.f);
        float rstd = rsqrtf(r.y * (1.f / 65536.f) - mean * mean + 1e-5f);
        g_m3[bg] = mean; g_r3[bg] = rstd;
    }
}

// ---------------- K8: tconv4 2x2 s2, 48->12 (FFMA2), GN3 folded -------------
__global__ void __launch_bounds__(256) k_t4(const float* __restrict__ tk,
                                            const float* __restrict__ tb,
                                            const float* __restrict__ g3g,
                                            const float* __restrict__ g3b) {
    __shared__ float sw[2304];                   // folded [d][ic][oc][q]
    __shared__ float sbias[2][12][2];
    __shared__ float sA[48], sB[48];
    int t = threadIdx.x;
    int b = blockIdx.x >> 6;

    if (t < 48) {
        int g = t >> 3;
        float A = g_r3[b * 6 + g] * g3g[t];
        sA[t] = A;
        sB[t] = g3b[t] - g_m3[b * 6 + g] * A;
    }
    __syncthreads();
    for (int i = t; i < 2304; i += 256) {
        int q = i & 1, d = (i >> 1) & 1, oc = (i >> 2) % 12, ic = i / 48;
        sw[((d * 48 + ic) * 12 + oc) * 2 + q] = sA[ic] * tk[i];
    }
    if (t < 48) {
        int q = t & 1, d = (t >> 1) & 1, oc = t >> 2;
        float bsum = tb[oc];
        for (int ic = 0; ic < 48; ic++)
            bsum = fmaf(sB[ic], tk[((ic * 12 + oc) * 2 + d) * 2 + q], bsum);
        sbias[d][oc][q] = bsum;
    }
    __syncthreads();

    int idx = blockIdx.x * 256 + t;              // 64*128*128
    int wi = idx & 127, h = (idx >> 7) & 127;
    int d = h & 1, hi = h >> 1;
    u64 acc[12];
    u64 z = pk2(0.f, 0.f);
#pragma unroll
    for (int i = 0; i < 12; i++) acc[i] = z;

    const float* c2b = g_c2 + (size_t)b * 24 * 8192 + hi * 128 + wi;
    const float* u3b = g_u3 + (size_t)b * 24 * 8192 + hi * 128 + wi;
    const u64* wb = (const u64*)(sw + d * 48 * 24);
#pragma unroll 6
    for (int ic = 0; ic < 24; ic++) {
        float v = c2b[(size_t)ic * 8192];
        u64 vv = pk2(v, v);
        const u64* wp = wb + ic * 12;
#pragma unroll
        for (int oc = 0; oc < 12; oc++) acc[oc] = ffma2(vv, wp[oc], acc[oc]);
    }
#pragma unroll 6
    for (int ic = 0; ic < 24; ic++) {
        float v = u3b[(size_t)ic * 8192];
        u64 vv = pk2(v, v);
        const u64* wp = wb + (24 + ic) * 12;
#pragma unroll
        for (int oc = 0; oc < 12; oc++) acc[oc] = ffma2(vv, wp[oc], acc[oc]);
    }
    __half* ob = g_u4h + (size_t)b * 12 * 32768 + (size_t)h * 256 + 2 * wi;
    float pv[24];
#pragma unroll
    for (int oc = 0; oc < 12; oc++) {
        float2 a = upk2(acc[oc]);
        float y0 = a.x + sbias[d][oc][0];
        float y1 = a.y + sbias[d][oc][1];
        __half2 h2 = __floats2half2_rn(y0, y1);
        *(__half2*)(ob + (size_t)oc * 32768) = h2;
        float2 yr = __half22float2(h2);
        pv[2 * oc] = yr.x + yr.y; pv[2 * oc + 1] = fmaf(yr.x, yr.x, yr.y * yr.y);
    }
    block_preduce<24>(pv, &g_part4[(size_t)blockIdx.x * 24]);
}

// ---------------- K9: gn4 stats reduce ---------------------------------------
__global__ void k_red4() {
    int bg = blockIdx.x; int b = bg / 6, g = bg % 6;
    float s = 0.f, s2 = 0.f;
    if (g < 2) {
        if (threadIdx.x < 3) {
            float2 v = g_sumc1[b * 6 + g * 3 + threadIdx.x];
            s = v.x; s2 = v.y;
        }
    } else {
        if (threadIdx.x < 192) {
            int j = threadIdx.x >> 6, blk = threadIdx.x & 63;
            int oc = (g - 2) * 3 + j;
            const float* p = &g_part4[(size_t)(b * 64 + blk) * 24 + oc * 2];
            s = p[0]; s2 = p[1];
        }
    }
    float2 r = block_reduce2(s, s2);
    if (threadIdx.x == 0) {
        float mean = r.x * (1.f / 98304.f);
        float rstd = rsqrtf(r.y * (1.f / 98304.f) - mean * mean + 1e-5f);
        g_m4[bg] = mean; g_r4[bg] = rstd;
    }
}

// ---------------- K10: GN4-apply + t5 1x1 (18->6, FFMA2) --------------------
__global__ void __launch_bounds__(256) k_gn4t5(const float* __restrict__ g4g,
                                               const float* __restrict__ g4b,
                                               const float* __restrict__ t5k,
                                               const float* __restrict__ t5b) {
    __shared__ float W2[18][6];                  // rows 24B apart -> pairs aligned
    __shared__ float cst[6];
    int t = threadIdx.x;
    int b  = blockIdx.x >> 7;
    int sp = ((blockIdx.x & 127) << 8) + t;

    if (t < 108) {
        int c = t / 6, o = t % 6;
        float A = g_r4[b * 6 + c / 3] * g4g[c];
        W2[c][o] = A * t5k[o * 18 + c];
    }
    if (t >= 128 && t < 134) {
        int o = t - 128;
        float cc = t5b[o];
        for (int c = 0; c < 18; c++) {
            float A  = g_r4[b * 6 + c / 3] * g4g[c];
            float Bv = g4b[c] - g_m4[b * 6 + c / 3] * A;
            cc = fmaf(Bv, t5k[o * 18 + c], cc);
        }
        cst[o] = cc;
    }
    __syncthreads();

    u64 acc[3];
    acc[0] = pk2(cst[0], cst[1]);
    acc[1] = pk2(cst[2], cst[3]);
    acc[2] = pk2(cst[4], cst[5]);
    const __half* c1b = g_c1h + (size_t)b * 6 * 32768 + sp;
    const __half* u4b = g_u4h + (size_t)b * 12 * 32768 + sp;
#pragma unroll
    for (int c = 0; c < 18; c++) {
        float v = __half2float((c < 6) ? c1b[(size_t)c * 32768] : u4b[(size_t)(c - 6) * 32768]);
        u64 vv = pk2(v, v);
        const u64* wp = (const u64*)&W2[c][0];
#pragma unroll
        for (int j = 0; j < 3; j++) acc[j] = ffma2(vv, wp[j], acc[j]);
    }
    float2 a0 = upk2(acc[0]), a1 = upk2(acc[1]), a2 = upk2(acc[2]);
    float* up = g_u5 + (size_t)b * 6 * 32768 + sp;
    up[0] = a0.x; up[32768] = a0.y; up[2 * 32768] = a1.x;
    up[3 * 32768] = a1.y; up[4 * 32768] = a2.x; up[5 * 32768] = a2.y;

    float pv[12];
    pv[0] = a0.x; pv[1] = a0.x * a0.x; pv[2]  = a0.y; pv[3]  = a0.y * a0.y;
    pv[4] = a1.x; pv[5] = a1.x * a1.x; pv[6]  = a1.y; pv[7]  = a1.y * a1.y;
    pv[8] = a2.x; pv[9] = a2.x * a2.x; pv[10] = a2.y; pv[11] = a2.y * a2.y;
    block_preduce<12>(pv, &g_part5[(size_t)blockIdx.x * 12]);
}

// ---------------- K11: gn5 stats reduce --------------------------------------
__global__ void k_red5() {
    int bc = blockIdx.x; int b = bc / 6, c = bc % 6;
    float s = 0.f, s2 = 0.f;
    if (threadIdx.x < 128) {
        const float* p = &g_part5[(size_t)(b * 128 + threadIdx.x) * 12 + 2 * c];
        s = p[0]; s2 = p[1];
    }
    float2 r = block_reduce2(s, s2);
    if (threadIdx.x == 0) {
        float mean = r.x * (1.f / 32768.f);
        float rstd = rsqrtf(r.y * (1.f / 32768.f) - mean * mean + 1e-5f);
        g_m5[bc] = mean; g_r5[bc] = rstd;
    }
}

// ---------------- K12: GN5-apply + final 1x1 + /std(t) ----------------------
__global__ void __launch_bounds__(256) k_final(const float* __restrict__ tt,
                                               const float* __restrict__ g5g,
                                               const float* __restrict__ g5b,
                                               const float* __restrict__ fk,
                                               const float* __restrict__ fb2,
                                               float* __restrict__ out) {
    __shared__ float coef[6];
    __shared__ float cshift, istd;
    int t = threadIdx.x;
    int b  = blockIdx.x >> 7;
    int sp = ((blockIdx.x & 127) << 8) + t;

    if (t < 6) {
        float A = g_r5[b * 6 + t] * g5g[t];
        coef[t] = A * fk[t];
    }
    if (t == 6) {
        float cc = fb2[0];
        for (int c = 0; c < 6; c++) {
            float A = g_r5[b * 6 + c] * g5g[c];
            cc = fmaf(g5b[c] - g_m5[b * 6 + c] * A, fk[c], cc);
        }
        cshift = cc;
    }
    if (t == 7) {
        float tv = tt[b];
        float s2v = (expf(tv * 6.437751649736401f) - 1.f) * (1.f / 6.437751649736401f);
        istd = rsqrtf(s2v);
    }
    __syncthreads();

    const float* up = g_u5 + (size_t)b * 6 * 32768 + sp;
    float v = cshift;
#pragma unroll
    for (int c = 0; c < 6; c++) v = fmaf(up[(size_t)c * 32768], coef[c], v);
    out[(size_t)b * 32768 + sp] = v * istd;
}

// ---------------- launcher ---------------------------------------------------
extern "C" void kernel_launch(void* const* d_in, const int* in_sizes, int n_in,
                              void* d_out, int out_size) {
    const float* x       = (const float*)d_in[0];
    const float* t       = (const float*)d_in[1];
    const float* Wf      = (const float*)d_in[2];
    const float* fc1_w   = (const float*)d_in[3];
    const float* fc1_b   = (const float*)d_in[4];
    const float* conv1_k = (const float*)d_in[5];
    const float* conv1_b = (const float*)d_in[6];
    const float* gn1_g   = (const float*)d_in[7];
    const float* gn1_b   = (const float*)d_in[8];
    const float* conv2_k = (const float*)d_in[9];
    const float* conv2_b = (const float*)d_in[10];
    const float* gn2_g   = (const float*)d_in[11];
    const float* gn2_b   = (const float*)d_in[12];
    const float* t3_k    = (const float*)d_in[13];
    const float* t3_b    = (const float*)d_in[14];
    const float* gn3_g   = (const float*)d_in[15];
    const float* gn3_b   = (const float*)d_in[16];
    const float* t4_k    = (const float*)d_in[17];
    const float* t4_b    = (const float*)d_in[18];
    const float* gn4_g   = (const float*)d_in[19];
    const float* gn4_b   = (const float*)d_in[20];
    const float* t5_k    = (const float*)d_in[21];
    const float* t5_b    = (const float*)d_in[22];
    const float* gn5_g   = (const float*)d_in[23];
    const float* gn5_b   = (const float*)d_in[24];
    const float* fin_k   = (const float*)d_in[25];
    const float* fin_b   = (const float*)d_in[26];
    float* out = (float*)d_out;

    k_prepw<<<128, 256>>>(fc1_w);
    k_fc1<<<512, 256>>>(x, Wf, fc1_b);
    k_conv1<<<8192, 256>>>(conv1_k, conv1_b);
    k_gnpool1<<<1536, 256>>>(gn1_g, gn1_b);
    k_conv2<<<2048, 256>>>(conv2_k, conv2_b);
    k_gnpool2<<<1536, 512>>>(gn2_g, gn2_b);
    k_t3<<<1024, 256>>>(t3_k, t3_b);
    k_red3<<<384, 128>>>();
    k_t4<<<4096, 256>>>(t4_k, t4_b, gn3_g, gn3_b);
    k_red4<<<384, 256>>>();
    k_gn4t5<<<8192, 256>>>(gn4_g, gn4_b, t5_k, t5_b);
    k_red5<<<384, 128>>>();
    k_final<<<8192, 256>>>(t, gn5_g, gn5_b, fin_k, fin_b, out);
}